// round 16
// baseline (speedup 1.0000x reference)
#include <cuda_runtime.h>
#include <cuda_fp16.h>
#include <math.h>
#include <stdint.h>

typedef unsigned long long ull;

#define NB 32
#define C 128
#define HW 4096
#define K 64
#define KE 56
#define TP 128
#define NTILES 32
#define TPB 4                       // tiles per block
#define NCHUNK (NTILES / TPB)       // 8 partial chunks
#define NTHR 256

#define RB 272            // row bytes (136 halfs); 4-bank shift per row

// dynamic smem; a' overlays XT_LO (dead after GEMM1) so W persists across tiles
#define XT_HI 0           // xT[p][c] hi  128*272 = 34816
#define XT_LO 34816       // xT[p][c] lo -> a'[k][p] after GEMM1
#define W_HI  69632       // W[k][c] hi (persistent)
#define W_LO  87040       // W[k][c] lo (persistent)
#define SMEM_DYN 104448   // 102 KB -> 2 CTAs/SM

__device__ float g_part[NB * NCHUNK * KE * C];      // 7.3 MB
__device__ float g_asum_part[NB * NCHUNK * K];
__device__ float g_vlad[NB * KE * C];

__device__ __forceinline__ uint32_t smem_u32(const void* p) {
    uint32_t a;
    asm("{ .reg .u64 t; cvta.to.shared.u64 t, %1; cvt.u32.u64 %0, t; }" : "=r"(a) : "l"(p));
    return a;
}
__device__ __forceinline__ void ldsm_x4(uint32_t a, uint32_t* r) {
    asm volatile("ldmatrix.sync.aligned.m8n8.x4.shared.b16 {%0,%1,%2,%3}, [%4];"
                 : "=r"(r[0]), "=r"(r[1]), "=r"(r[2]), "=r"(r[3]) : "r"(a));
}
__device__ __forceinline__ void ldsm_x4t(uint32_t a, uint32_t* r) {
    asm volatile("ldmatrix.sync.aligned.m8n8.x4.trans.shared.b16 {%0,%1,%2,%3}, [%4];"
                 : "=r"(r[0]), "=r"(r[1]), "=r"(r[2]), "=r"(r[3]) : "r"(a));
}
__device__ __forceinline__ void mma16816(float* d, const uint32_t* a, uint32_t b0, uint32_t b1) {
    asm volatile("mma.sync.aligned.m16n8k16.row.col.f32.f16.f16.f32 "
                 "{%0,%1,%2,%3}, {%4,%5,%6,%7}, {%8,%9}, {%0,%1,%2,%3};"
                 : "+f"(d[0]), "+f"(d[1]), "+f"(d[2]), "+f"(d[3])
                 : "r"(a[0]), "r"(a[1]), "r"(a[2]), "r"(a[3]), "r"(b0), "r"(b1));
}
__device__ __forceinline__ uint32_t h2u(__half2 h) { return *reinterpret_cast<uint32_t*>(&h); }

// GEMM1: 3 split passes, issued as 3 sweeps of 8 independent MMAs (ILP)
__device__ __forceinline__ void gemm_nn(const uint32_t smb, int wm, int wn, int lane,
                                        float d[8][4]) {
    const uint32_t lo16 = lane & 15;
    const uint32_t sel = (lane >> 4) * 16;
    const uint32_t aOff = (wm * 32 + lo16) * RB + sel;
    const uint32_t bOff = (wn * 32 + lo16) * RB + sel;
#pragma unroll
    for (int ks = 0; ks < 8; ++ks) {
        const uint32_t kb = ks * 32;
        uint32_t ah[8], al[8], bh[8], bl[8];
        ldsm_x4(smb + W_HI + aOff + kb, ah);
        ldsm_x4(smb + W_HI + aOff + 16 * RB + kb, ah + 4);
        ldsm_x4(smb + W_LO + aOff + kb, al);
        ldsm_x4(smb + W_LO + aOff + 16 * RB + kb, al + 4);
        ldsm_x4(smb + XT_HI + bOff + kb, bh);
        ldsm_x4(smb + XT_HI + bOff + 16 * RB + kb, bh + 4);
        ldsm_x4(smb + XT_LO + bOff + kb, bl);
        ldsm_x4(smb + XT_LO + bOff + 16 * RB + kb, bl + 4);
#pragma unroll
        for (int mt = 0; mt < 2; ++mt)
#pragma unroll
            for (int f = 0; f < 4; ++f) {
                const int bi = (f >> 1) * 4 + (f & 1);
                mma16816(d[mt * 4 + f], ah + mt * 4, bh[bi], bh[bi + 2]);
            }
#pragma unroll
        for (int mt = 0; mt < 2; ++mt)
#pragma unroll
            for (int f = 0; f < 4; ++f) {
                const int bi = (f >> 1) * 4 + (f & 1);
                mma16816(d[mt * 4 + f], al + mt * 4, bh[bi], bh[bi + 2]);
            }
#pragma unroll
        for (int mt = 0; mt < 2; ++mt)
#pragma unroll
            for (int f = 0; f < 4; ++f) {
                const int bi = (f >> 1) * 4 + (f & 1);
                mma16816(d[mt * 4 + f], ah + mt * 4, bl[bi], bl[bi + 2]);
            }
    }
}

// GEMM2 (single hi*hi pass; A = a'[k][p] at XT_LO; B = xT_hi via trans ldmatrix)
__device__ __forceinline__ void gemm_nt(const uint32_t smb, int wm, int wn, int lane,
                                        float d[8][4]) {
    const uint32_t lo16 = lane & 15;
    const uint32_t sel = (lane >> 4) * 16;
    const uint32_t aOff = (wm * 32 + lo16) * RB + sel;
    const uint32_t brow = (lane & 7) + ((lane >> 4) << 3);
    const uint32_t bOff = brow * RB + (wn * 32 + ((lane >> 3) & 1) * 8) * 2;
#pragma unroll
    for (int ks = 0; ks < 8; ++ks) {
        const uint32_t kb = ks * 32;
        const uint32_t bb = ks * 16 * RB;
        uint32_t ah[8], bh[8];
        ldsm_x4(smb + XT_LO + aOff + kb, ah);
        ldsm_x4(smb + XT_LO + aOff + 16 * RB + kb, ah + 4);
        ldsm_x4t(smb + XT_HI + bOff + bb, bh);
        ldsm_x4t(smb + XT_HI + bOff + bb + 32, bh + 4);
#pragma unroll
        for (int mt = 0; mt < 2; ++mt)
#pragma unroll
            for (int f = 0; f < 4; ++f) {
                const int bi = (f >> 1) * 4 + (f & 1);
                mma16816(d[mt * 4 + f], ah + mt * 4, bh[bi], bh[bi + 2]);
            }
    }
}

__global__ __launch_bounds__(NTHR, 2)
void netvlad_mma(const float* __restrict__ x,
                 const float* __restrict__ conv_w,
                 const float* __restrict__ conv_b) {
    extern __shared__ unsigned char sm[];
    const uint32_t smb = smem_u32(sm);

    __shared__ float bs_s[K], rn_s[TP], ms_s[TP], sinv_s[TP];
    __shared__ float red2[2][TP];
    __shared__ float asw[8][32];

    const int n = blockIdx.x, chunk = blockIdx.y;
    const int tid = threadIdx.x, lane = tid & 31, w = tid >> 5;
    const int wm = w >> 2, wn = w & 3;
    const int k0 = wm * 32 + (lane >> 2);

    // ---- W fp32 -> fp16 hi/lo [k][c] once (persistent across tiles) ----
    for (int idx = tid; idx < K * C / 2; idx += NTHR) {
        int k = idx >> 6, c2 = (idx & 63) * 2;
        float v0 = __ldg(conv_w + k * C + c2);
        float v1 = __ldg(conv_w + k * C + c2 + 1);
        __half2 h = __float22half2_rn(make_float2(v0, v1));
        float2 hf = __half22float2(h);
        __half2 l = __float22half2_rn(make_float2(v0 - hf.x, v1 - hf.y));
        *(__half2*)(sm + W_HI + k * RB + c2 * 2) = h;
        *(__half2*)(sm + W_LO + k * RB + c2 * 2) = l;
    }
    if (tid < K) bs_s[tid] = conv_b[tid];

    float d2[8][4];
#pragma unroll
    for (int f = 0; f < 8; ++f)
#pragma unroll
        for (int e = 0; e < 4; ++e) d2[f][e] = 0.0f;
    float aks[4] = {0.f, 0.f, 0.f, 0.f};

    for (int tt = 0; tt < TPB; ++tt) {
        const int tile = chunk * TPB + tt;
        __syncthreads();   // tt=0: W visible; tt>0: GEMM2 done reading XT_* before overwrite

        // ---- load x, split fp16 hi/lo into xT[p][c], ssq ----
        {
            const int p = tid & 127, q = tid >> 7;
            const float* xp = x + (size_t)n * C * HW + (size_t)tile * TP + p;
            float ss = 0.0f;
#pragma unroll
            for (int g = 0; g < 8; ++g) {
                const int c = q * 64 + g * 8;
                float v[8];
#pragma unroll
                for (int j = 0; j < 8; ++j) v[j] = __ldg(xp + (size_t)(c + j) * HW);
#pragma unroll
                for (int j = 0; j < 8; ++j) ss += v[j] * v[j];
                uint4 hi, lo;
                {
                    __half2 h0 = __float22half2_rn(make_float2(v[0], v[1]));
                    __half2 h1 = __float22half2_rn(make_float2(v[2], v[3]));
                    __half2 h2 = __float22half2_rn(make_float2(v[4], v[5]));
                    __half2 h3 = __float22half2_rn(make_float2(v[6], v[7]));
                    hi = make_uint4(h2u(h0), h2u(h1), h2u(h2), h2u(h3));
                    float2 f0 = __half22float2(h0), f1 = __half22float2(h1);
                    float2 f2 = __half22float2(h2), f3 = __half22float2(h3);
                    lo = make_uint4(
                        h2u(__float22half2_rn(make_float2(v[0] - f0.x, v[1] - f0.y))),
                        h2u(__float22half2_rn(make_float2(v[2] - f1.x, v[3] - f1.y))),
                        h2u(__float22half2_rn(make_float2(v[4] - f2.x, v[5] - f2.y))),
                        h2u(__float22half2_rn(make_float2(v[6] - f3.x, v[7] - f3.y))));
                }
                *(uint4*)(sm + XT_HI + p * RB + c * 2) = hi;
                *(uint4*)(sm + XT_LO + p * RB + c * 2) = lo;
            }
            red2[q][p] = ss;
        }
        __syncthreads();
        if (tid < TP)
            rn_s[tid] = 1.0f / fmaxf(sqrtf(red2[0][tid] + red2[1][tid]), 1e-12f);
        __syncthreads();

        // ---- GEMM1 ----
        float d1[8][4];
#pragma unroll
        for (int f = 0; f < 8; ++f)
#pragma unroll
            for (int e = 0; e < 4; ++e) d1[f][e] = 0.0f;
        gemm_nn(smb, wm, wn, lane, d1);

        // ---- logits + softmax ----
        float bk[4] = {bs_s[k0], bs_s[k0 + 8], bs_s[k0 + 16], bs_s[k0 + 24]};
#pragma unroll
        for (int mt = 0; mt < 2; ++mt)
#pragma unroll
            for (int f = 0; f < 4; ++f) {
                const int p = wn * 32 + f * 8 + 2 * (lane & 3);
                const float r0 = rn_s[p], r1 = rn_s[p + 1];
                float* dd = d1[mt * 4 + f];
                dd[0] = dd[0] * r0 + bk[2 * mt];
                dd[1] = dd[1] * r1 + bk[2 * mt];
                dd[2] = dd[2] * r0 + bk[2 * mt + 1];
                dd[3] = dd[3] * r1 + bk[2 * mt + 1];
            }
#pragma unroll
        for (int f = 0; f < 4; ++f) {
            float m0 = fmaxf(fmaxf(d1[f][0], d1[f][2]), fmaxf(d1[4 + f][0], d1[4 + f][2]));
            float m1 = fmaxf(fmaxf(d1[f][1], d1[f][3]), fmaxf(d1[4 + f][1], d1[4 + f][3]));
#pragma unroll
            for (int off = 4; off <= 16; off <<= 1) {
                m0 = fmaxf(m0, __shfl_xor_sync(0xffffffffu, m0, off));
                m1 = fmaxf(m1, __shfl_xor_sync(0xffffffffu, m1, off));
            }
            if ((lane >> 2) == 0) {
                const int p = wn * 32 + f * 8 + 2 * lane;
                red2[wm][p] = m0;
                red2[wm][p + 1] = m1;
            }
        }
        __syncthreads();
        if (tid < TP) ms_s[tid] = fmaxf(red2[0][tid], red2[1][tid]);
        __syncthreads();

#pragma unroll
        for (int f = 0; f < 4; ++f) {
            const int p = wn * 32 + f * 8 + 2 * (lane & 3);
            const float M0 = ms_s[p], M1 = ms_s[p + 1];
#pragma unroll
            for (int mt = 0; mt < 2; ++mt) {
                float* dd = d1[mt * 4 + f];
                dd[0] = __expf(dd[0] - M0);
                dd[1] = __expf(dd[1] - M1);
                dd[2] = __expf(dd[2] - M0);
                dd[3] = __expf(dd[3] - M1);
            }
            float s0 = d1[f][0] + d1[f][2] + d1[4 + f][0] + d1[4 + f][2];
            float s1 = d1[f][1] + d1[f][3] + d1[4 + f][1] + d1[4 + f][3];
#pragma unroll
            for (int off = 4; off <= 16; off <<= 1) {
                s0 += __shfl_xor_sync(0xffffffffu, s0, off);
                s1 += __shfl_xor_sync(0xffffffffu, s1, off);
            }
            if ((lane >> 2) == 0) {
                const int p2 = wn * 32 + f * 8 + 2 * lane;
                red2[wm][p2] = s0;
                red2[wm][p2 + 1] = s1;
            }
        }
        __syncthreads();
        if (tid < TP) sinv_s[tid] = 1.0f / (red2[0][tid] + red2[1][tid]);
        __syncthreads();   // XT_LO dead, overlay a'

        // ---- a = e*sinv; accumulate aks; a' = a*rn (hi) into XT_LO ----
#pragma unroll
        for (int mt = 0; mt < 2; ++mt)
#pragma unroll
            for (int f = 0; f < 4; ++f) {
                const int p = wn * 32 + f * 8 + 2 * (lane & 3);
                const float s0 = sinv_s[p], s1 = sinv_s[p + 1];
                const float r0 = rn_s[p], r1 = rn_s[p + 1];
                float* dd = d1[mt * 4 + f];
                const float a00 = dd[0] * s0, a01 = dd[1] * s1;
                const float a10 = dd[2] * s0, a11 = dd[3] * s1;
                aks[2 * mt] += a00 + a01;
                aks[2 * mt + 1] += a10 + a11;
                __half2 h0 = __float22half2_rn(make_float2(a00 * r0, a01 * r1));
                __half2 h1 = __float22half2_rn(make_float2(a10 * r0, a11 * r1));
                const int kr = k0 + 16 * mt;
                *(__half2*)(sm + XT_LO + kr * RB + p * 2) = h0;
                *(__half2*)(sm + XT_LO + (kr + 8) * RB + p * 2) = h1;
            }
        __syncthreads();   // a' visible to all warps

        // ---- GEMM2 accumulate across tiles ----
        gemm_nt(smb, wm, wn, lane, d2);
    }

    // ---- asum exchange + store (once per block) ----
#pragma unroll
    for (int i = 0; i < 4; ++i) {
        aks[i] += __shfl_xor_sync(0xffffffffu, aks[i], 1);
        aks[i] += __shfl_xor_sync(0xffffffffu, aks[i], 2);
    }
    if ((lane & 3) == 0) {
        const int r = lane >> 2;
        asw[w][r] = aks[0];
        asw[w][8 + r] = aks[1];
        asw[w][16 + r] = aks[2];
        asw[w][24 + r] = aks[3];
    }
    __syncthreads();
    if (tid < K) {
        const int wmk = tid >> 5, kk = tid & 31;
        g_asum_part[(n * NCHUNK + chunk) * K + tid] =
            asw[wmk * 4 + 0][kk] + asw[wmk * 4 + 1][kk] +
            asw[wmk * 4 + 2][kk] + asw[wmk * 4 + 3][kk];
    }

    // ---- store accumulated partial [k][c], k < KE only ----
    {
        float* gp = g_part + (size_t)(n * NCHUNK + chunk) * KE * C;
#pragma unroll
        for (int mt = 0; mt < 2; ++mt)
#pragma unroll
            for (int f = 0; f < 4; ++f) {
                const int c = wn * 32 + f * 8 + 2 * (lane & 3);
                const int kr = k0 + 16 * mt;
                float* dd = d2[mt * 4 + f];
                *(float2*)(gp + kr * C + c) = make_float2(dd[0], dd[1]);
                if (kr + 8 < KE)
                    *(float2*)(gp + (kr + 8) * C + c) = make_float2(dd[2], dd[3]);
            }
    }
}

__global__ __launch_bounds__(256)
void reduce_part() {
    const int n = blockIdx.x;
    const int idx = blockIdx.y * 256 + threadIdx.x;   // 0..1791 float4 units (KE*C/4)
    const float4* src = (const float4*)g_part + (size_t)n * NCHUNK * 1792 + idx;
    float4 acc = make_float4(0.f, 0.f, 0.f, 0.f);
#pragma unroll 8
    for (int t = 0; t < NCHUNK; ++t) {
        float4 v = src[(size_t)t * 1792];
        acc.x += v.x; acc.y += v.y; acc.z += v.z; acc.w += v.w;
    }
    ((float4*)g_vlad)[(size_t)n * 1792 + idx] = acc;
}

__global__ __launch_bounds__(512)
void netvlad_finalize(const float* __restrict__ centroids, float* __restrict__ out) {
    __shared__ float ys[KE * C];       // 28 KB
    __shared__ float colss[16][C];     // 8 KB
    __shared__ float colinv[C];
    __shared__ float asl[KE];
    __shared__ float red[4];
    __shared__ float s_inv2;

    const int n = blockIdx.x, tid = threadIdx.x;

    if (tid < KE) {
        float s = 0.0f;
        const float* ap = g_asum_part + (size_t)n * NCHUNK * K + tid;
#pragma unroll
        for (int t = 0; t < NCHUNK; ++t) s += ap[t * K];
        asl[tid] = s;
    }
    __syncthreads();

    const int cg = (tid & 31) * 4;
    float4 ss4 = make_float4(0.f, 0.f, 0.f, 0.f);
#pragma unroll
    for (int r = 0; r < 4; ++r) {
        int e4 = tid + r * 512;
        if (e4 < 1792) {
            int k = e4 >> 5;
            float a = asl[k];
            float4 s = ((const float4*)g_vlad)[(size_t)n * 1792 + e4];
            float4 ce = *(const float4*)(centroids + k * C + cg);
            float4 y;
            y.x = s.x - a * ce.x; y.y = s.y - a * ce.y;
            y.z = s.z - a * ce.z; y.w = s.w - a * ce.w;
            *(float4*)(ys + e4 * 4) = y;
            ss4.x += y.x * y.x; ss4.y += y.y * y.y;
            ss4.z += y.z * y.z; ss4.w += y.w * y.w;
        }
    }
    *(float4*)&colss[tid >> 5][cg] = ss4;
    __syncthreads();

    float gs = 0.0f;
    if (tid < C) {
        float cs = 0.0f;
#pragma unroll
        for (int g = 0; g < 16; ++g) cs += colss[g][tid];
        float i1 = 1.0f / fmaxf(sqrtf(cs), 1e-12f);
        gs = cs * i1 * i1;
        colinv[tid] = i1;
    }
    __syncthreads();
#pragma unroll
    for (int off = 16; off; off >>= 1) gs += __shfl_down_sync(0xffffffffu, gs, off);
    if (tid < C && (tid & 31) == 0) red[tid >> 5] = gs;
    __syncthreads();
    if (tid == 0) {
        float t = red[0] + red[1] + red[2] + red[3];
        s_inv2 = 1.0f / fmaxf(sqrtf(t), 1e-12f);
    }
    __syncthreads();
    const float inv2 = s_inv2;
    float* op = out + (size_t)n * KE * C;
    for (int idx = tid; idx < KE * C; idx += 512)
        op[idx] = ys[idx] * colinv[idx & 127] * inv2;
}

extern "C" void kernel_launch(void* const* d_in, const int* in_sizes, int n_in,
                              void* d_out, int out_size) {
    const float* x      = (const float*)d_in[0];
    const float* conv_w = (const float*)d_in[1];
    const float* conv_b = (const float*)d_in[2];
    const float* cen    = (const float*)d_in[3];
    float* out = (float*)d_out;

    cudaFuncSetAttribute(netvlad_mma, cudaFuncAttributeMaxDynamicSharedMemorySize, SMEM_DYN);

    netvlad_mma<<<dim3(NB, NCHUNK), NTHR, SMEM_DYN>>>(x, conv_w, conv_b);
    reduce_part<<<dim3(NB, 7), 256>>>();
    netvlad_finalize<<<NB, 512>>>(cen, out);
}

// round 17
// speedup vs baseline: 1.0024x; 1.0024x over previous
#include <cuda_runtime.h>
#include <cuda_fp16.h>
#include <math.h>
#include <stdint.h>

typedef unsigned long long ull;

#define NB 32
#define C 128
#define HW 4096
#define K 64
#define KE 56
#define TP 128
#define NTILES 32
#define TPB 8                       // tiles per block
#define NCHUNK (NTILES / TPB)       // 4 partial chunks
#define NTHR 512                    // 8 consumer + 8 producer warps

#define RB 272            // row bytes (136 halfs); 4-bank shift per row

// double-buffered xT + persistent W
#define XT0_HI 0
#define XT0_LO 34816
#define XT1_HI 69632
#define XT1_LO 104448
#define W_HI   139264
#define W_LO   156672
#define SMEM_DYN 174080   // 170 KB -> 1 CTA/SM

__device__ float g_part[NB * NCHUNK * KE * C];      // 3.7 MB
__device__ float g_asum_part[NB * NCHUNK * K];
__device__ float g_vlad[NB * KE * C];

// named barriers: 1 = consumer-internal(256); 2,3 = FULL(buf0/1); 4,5 = EMPTY(buf0/1)
#define CBAR() asm volatile("bar.sync 1, 256;" ::: "memory")
#define BAR_SYNC(id) asm volatile("bar.sync %0, 512;" :: "r"(id) : "memory")
#define BAR_ARRIVE(id) asm volatile("bar.arrive %0, 512;" :: "r"(id) : "memory")

__device__ __forceinline__ uint32_t smem_u32(const void* p) {
    uint32_t a;
    asm("{ .reg .u64 t; cvta.to.shared.u64 t, %1; cvt.u32.u64 %0, t; }" : "=r"(a) : "l"(p));
    return a;
}
__device__ __forceinline__ void ldsm_x4(uint32_t a, uint32_t* r) {
    asm volatile("ldmatrix.sync.aligned.m8n8.x4.shared.b16 {%0,%1,%2,%3}, [%4];"
                 : "=r"(r[0]), "=r"(r[1]), "=r"(r[2]), "=r"(r[3]) : "r"(a));
}
__device__ __forceinline__ void ldsm_x4t(uint32_t a, uint32_t* r) {
    asm volatile("ldmatrix.sync.aligned.m8n8.x4.trans.shared.b16 {%0,%1,%2,%3}, [%4];"
                 : "=r"(r[0]), "=r"(r[1]), "=r"(r[2]), "=r"(r[3]) : "r"(a));
}
__device__ __forceinline__ void mma16816(float* d, const uint32_t* a, uint32_t b0, uint32_t b1) {
    asm volatile("mma.sync.aligned.m16n8k16.row.col.f32.f16.f16.f32 "
                 "{%0,%1,%2,%3}, {%4,%5,%6,%7}, {%8,%9}, {%0,%1,%2,%3};"
                 : "+f"(d[0]), "+f"(d[1]), "+f"(d[2]), "+f"(d[3])
                 : "r"(a[0]), "r"(a[1]), "r"(a[2]), "r"(a[3]), "r"(b0), "r"(b1));
}
__device__ __forceinline__ uint32_t h2u(__half2 h) { return *reinterpret_cast<uint32_t*>(&h); }

// GEMM1: 3 split passes, 3 sweeps of 8 independent MMAs
__device__ __forceinline__ void gemm_nn(const uint32_t smb, uint32_t xthi, uint32_t xtlo,
                                        int wm, int wn, int lane, float d[8][4]) {
    const uint32_t lo16 = lane & 15;
    const uint32_t sel = (lane >> 4) * 16;
    const uint32_t aOff = (wm * 32 + lo16) * RB + sel;
    const uint32_t bOff = (wn * 32 + lo16) * RB + sel;
#pragma unroll
    for (int ks = 0; ks < 8; ++ks) {
        const uint32_t kb = ks * 32;
        uint32_t ah[8], al[8], bh[8], bl[8];
        ldsm_x4(smb + W_HI + aOff + kb, ah);
        ldsm_x4(smb + W_HI + aOff + 16 * RB + kb, ah + 4);
        ldsm_x4(smb + W_LO + aOff + kb, al);
        ldsm_x4(smb + W_LO + aOff + 16 * RB + kb, al + 4);
        ldsm_x4(smb + xthi + bOff + kb, bh);
        ldsm_x4(smb + xthi + bOff + 16 * RB + kb, bh + 4);
        ldsm_x4(smb + xtlo + bOff + kb, bl);
        ldsm_x4(smb + xtlo + bOff + 16 * RB + kb, bl + 4);
#pragma unroll
        for (int mt = 0; mt < 2; ++mt)
#pragma unroll
            for (int f = 0; f < 4; ++f) {
                const int bi = (f >> 1) * 4 + (f & 1);
                mma16816(d[mt * 4 + f], ah + mt * 4, bh[bi], bh[bi + 2]);
            }
#pragma unroll
        for (int mt = 0; mt < 2; ++mt)
#pragma unroll
            for (int f = 0; f < 4; ++f) {
                const int bi = (f >> 1) * 4 + (f & 1);
                mma16816(d[mt * 4 + f], al + mt * 4, bh[bi], bh[bi + 2]);
            }
#pragma unroll
        for (int mt = 0; mt < 2; ++mt)
#pragma unroll
            for (int f = 0; f < 4; ++f) {
                const int bi = (f >> 1) * 4 + (f & 1);
                mma16816(d[mt * 4 + f], ah + mt * 4, bl[bi], bl[bi + 2]);
            }
    }
}

// GEMM2 (single hi*hi; A = a'[k][p] in xtlo; B = xT_hi via trans ldmatrix)
__device__ __forceinline__ void gemm_nt(const uint32_t smb, uint32_t xthi, uint32_t xtlo,
                                        int wm, int wn, int lane, float d[8][4]) {
    const uint32_t lo16 = lane & 15;
    const uint32_t sel = (lane >> 4) * 16;
    const uint32_t aOff = (wm * 32 + lo16) * RB + sel;
    const uint32_t brow = (lane & 7) + ((lane >> 4) << 3);
    const uint32_t bOff = brow * RB + (wn * 32 + ((lane >> 3) & 1) * 8) * 2;
#pragma unroll
    for (int ks = 0; ks < 8; ++ks) {
        const uint32_t kb = ks * 32;
        const uint32_t bb = ks * 16 * RB;
        uint32_t ah[8], bh[8];
        ldsm_x4(smb + xtlo + aOff + kb, ah);
        ldsm_x4(smb + xtlo + aOff + 16 * RB + kb, ah + 4);
        ldsm_x4t(smb + xthi + bOff + bb, bh);
        ldsm_x4t(smb + xthi + bOff + bb + 32, bh + 4);
#pragma unroll
        for (int mt = 0; mt < 2; ++mt)
#pragma unroll
            for (int f = 0; f < 4; ++f) {
                const int bi = (f >> 1) * 4 + (f & 1);
                mma16816(d[mt * 4 + f], ah + mt * 4, bh[bi], bh[bi + 2]);
            }
    }
}

__global__ __launch_bounds__(NTHR, 1)
void netvlad_mma(const float* __restrict__ x,
                 const float* __restrict__ conv_w,
                 const float* __restrict__ conv_b) {
    extern __shared__ unsigned char sm[];
    const uint32_t smb = smem_u32(sm);

    __shared__ float bs_s[K], rn_s[TP], ms_s[TP], sinv_s[TP];
    __shared__ float red2[2][2][TP];   // [buf][q][p] producer ssq
    __shared__ float cred[2][TP];      // consumer softmax scratch
    __shared__ float asw[8][32];

    const int n = blockIdx.x, chunk = blockIdx.y;
    const int tid = threadIdx.x, lane = tid & 31, w = tid >> 5;

    // ---- W fp32 -> fp16 hi/lo (all 512 threads), then split roles ----
    for (int idx = tid; idx < K * C / 2; idx += NTHR) {
        int k = idx >> 6, c2 = (idx & 63) * 2;
        float v0 = __ldg(conv_w + k * C + c2);
        float v1 = __ldg(conv_w + k * C + c2 + 1);
        __half2 h = __float22half2_rn(make_float2(v0, v1));
        float2 hf = __half22float2(h);
        __half2 l = __float22half2_rn(make_float2(v0 - hf.x, v1 - hf.y));
        *(__half2*)(sm + W_HI + k * RB + c2 * 2) = h;
        *(__half2*)(sm + W_LO + k * RB + c2 * 2) = l;
    }
    if (tid < K) bs_s[tid] = conv_b[tid];
    __syncthreads();   // last full-block sync; roles diverge below

    if (w >= 8) {
        // ================= PRODUCER (warps 8-15) =================
        const int pt = tid - 256;
        const int p = pt & 127, q = pt >> 7;
        for (int tt = 0; tt < TPB; ++tt) {
            const int b = tt & 1;
            const uint32_t xthi = b ? XT1_HI : XT0_HI;
            const uint32_t xtlo = b ? XT1_LO : XT0_LO;
            if (tt >= 2) BAR_SYNC(4 + b);   // wait buffer free
            const int tile = chunk * TPB + tt;
            const float* xp = x + (size_t)n * C * HW + (size_t)tile * TP + p;
            float ss = 0.0f;
#pragma unroll
            for (int g = 0; g < 8; ++g) {
                const int c = q * 64 + g * 8;
                float v[8];
#pragma unroll
                for (int j = 0; j < 8; ++j) v[j] = __ldg(xp + (size_t)(c + j) * HW);
#pragma unroll
                for (int j = 0; j < 8; ++j) ss += v[j] * v[j];
                uint4 hi, lo;
                {
                    __half2 h0 = __float22half2_rn(make_float2(v[0], v[1]));
                    __half2 h1 = __float22half2_rn(make_float2(v[2], v[3]));
                    __half2 h2 = __float22half2_rn(make_float2(v[4], v[5]));
                    __half2 h3 = __float22half2_rn(make_float2(v[6], v[7]));
                    hi = make_uint4(h2u(h0), h2u(h1), h2u(h2), h2u(h3));
                    float2 f0 = __half22float2(h0), f1 = __half22float2(h1);
                    float2 f2 = __half22float2(h2), f3 = __half22float2(h3);
                    lo = make_uint4(
                        h2u(__float22half2_rn(make_float2(v[0] - f0.x, v[1] - f0.y))),
                        h2u(__float22half2_rn(make_float2(v[2] - f1.x, v[3] - f1.y))),
                        h2u(__float22half2_rn(make_float2(v[4] - f2.x, v[5] - f2.y))),
                        h2u(__float22half2_rn(make_float2(v[6] - f3.x, v[7] - f3.y))));
                }
                *(uint4*)(sm + xthi + p * RB + c * 2) = hi;
                *(uint4*)(sm + xtlo + p * RB + c * 2) = lo;
            }
            red2[b][q][p] = ss;
            BAR_ARRIVE(2 + b);   // buffer full
        }
        return;
    }

    // ================= CONSUMER (warps 0-7) =================
    const int wm = w >> 2, wn = w & 3;
    const int k0 = wm * 32 + (lane >> 2);

    float d2[8][4];
#pragma unroll
    for (int f = 0; f < 8; ++f)
#pragma unroll
        for (int e = 0; e < 4; ++e) d2[f][e] = 0.0f;
    float aks[4] = {0.f, 0.f, 0.f, 0.f};

    for (int tt = 0; tt < TPB; ++tt) {
        const int b = tt & 1;
        const uint32_t xthi = b ? XT1_HI : XT0_HI;
        const uint32_t xtlo = b ? XT1_LO : XT0_LO;
        BAR_SYNC(2 + b);   // wait buffer full

        if (tid < TP)
            rn_s[tid] = 1.0f / fmaxf(sqrtf(red2[b][0][tid] + red2[b][1][tid]), 1e-12f);
        CBAR();

        // ---- GEMM1 ----
        float d1[8][4];
#pragma unroll
        for (int f = 0; f < 8; ++f)
#pragma unroll
            for (int e = 0; e < 4; ++e) d1[f][e] = 0.0f;
        gemm_nn(smb, xthi, xtlo, wm, wn, lane, d1);

        // ---- logits + softmax ----
        float bk[4] = {bs_s[k0], bs_s[k0 + 8], bs_s[k0 + 16], bs_s[k0 + 24]};
#pragma unroll
        for (int mt = 0; mt < 2; ++mt)
#pragma unroll
            for (int f = 0; f < 4; ++f) {
                const int p = wn * 32 + f * 8 + 2 * (lane & 3);
                const float r0 = rn_s[p], r1 = rn_s[p + 1];
                float* dd = d1[mt * 4 + f];
                dd[0] = dd[0] * r0 + bk[2 * mt];
                dd[1] = dd[1] * r1 + bk[2 * mt];
                dd[2] = dd[2] * r0 + bk[2 * mt + 1];
                dd[3] = dd[3] * r1 + bk[2 * mt + 1];
            }
#pragma unroll
        for (int f = 0; f < 4; ++f) {
            float m0 = fmaxf(fmaxf(d1[f][0], d1[f][2]), fmaxf(d1[4 + f][0], d1[4 + f][2]));
            float m1 = fmaxf(fmaxf(d1[f][1], d1[f][3]), fmaxf(d1[4 + f][1], d1[4 + f][3]));
#pragma unroll
            for (int off = 4; off <= 16; off <<= 1) {
                m0 = fmaxf(m0, __shfl_xor_sync(0xffffffffu, m0, off));
                m1 = fmaxf(m1, __shfl_xor_sync(0xffffffffu, m1, off));
            }
            if ((lane >> 2) == 0) {
                const int p = wn * 32 + f * 8 + 2 * lane;
                cred[wm][p] = m0;
                cred[wm][p + 1] = m1;
            }
        }
        CBAR();
        if (tid < TP) ms_s[tid] = fmaxf(cred[0][tid], cred[1][tid]);
        CBAR();

#pragma unroll
        for (int f = 0; f < 4; ++f) {
            const int p = wn * 32 + f * 8 + 2 * (lane & 3);
            const float M0 = ms_s[p], M1 = ms_s[p + 1];
#pragma unroll
            for (int mt = 0; mt < 2; ++mt) {
                float* dd = d1[mt * 4 + f];
                dd[0] = __expf(dd[0] - M0);
                dd[1] = __expf(dd[1] - M1);
                dd[2] = __expf(dd[2] - M0);
                dd[3] = __expf(dd[3] - M1);
            }
            float s0 = d1[f][0] + d1[f][2] + d1[4 + f][0] + d1[4 + f][2];
            float s1 = d1[f][1] + d1[f][3] + d1[4 + f][1] + d1[4 + f][3];
#pragma unroll
            for (int off = 4; off <= 16; off <<= 1) {
                s0 += __shfl_xor_sync(0xffffffffu, s0, off);
                s1 += __shfl_xor_sync(0xffffffffu, s1, off);
            }
            if ((lane >> 2) == 0) {
                const int p2 = wn * 32 + f * 8 + 2 * lane;
                cred[wm][p2] = s0;
                cred[wm][p2 + 1] = s1;
            }
        }
        CBAR();
        if (tid < TP) sinv_s[tid] = 1.0f / (cred[0][tid] + cred[1][tid]);
        CBAR();   // all consumers past GEMM1: xtlo dead, overlay a'

        // ---- a = e*sinv; accumulate aks; a' = a*rn (hi) into xtlo ----
#pragma unroll
        for (int mt = 0; mt < 2; ++mt)
#pragma unroll
            for (int f = 0; f < 4; ++f) {
                const int p = wn * 32 + f * 8 + 2 * (lane & 3);
                const float s0 = sinv_s[p], s1 = sinv_s[p + 1];
                const float r0 = rn_s[p], r1 = rn_s[p + 1];
                float* dd = d1[mt * 4 + f];
                const float a00 = dd[0] * s0, a01 = dd[1] * s1;
                const float a10 = dd[2] * s0, a11 = dd[3] * s1;
                aks[2 * mt] += a00 + a01;
                aks[2 * mt + 1] += a10 + a11;
                __half2 h0 = __float22half2_rn(make_float2(a00 * r0, a01 * r1));
                __half2 h1 = __float22half2_rn(make_float2(a10 * r0, a11 * r1));
                const int kr = k0 + 16 * mt;
                *(__half2*)(sm + xtlo + kr * RB + p * 2) = h0;
                *(__half2*)(sm + xtlo + (kr + 8) * RB + p * 2) = h1;
            }
        CBAR();   // a' visible to all consumers

        // ---- GEMM2 accumulate ----
        gemm_nt(smb, xthi, xtlo, wm, wn, lane, d2);

        if (tt + 2 < TPB) BAR_ARRIVE(4 + b);   // buffer free for producer
    }

    // ---- asum exchange + store ----
#pragma unroll
    for (int i = 0; i < 4; ++i) {
        aks[i] += __shfl_xor_sync(0xffffffffu, aks[i], 1);
        aks[i] += __shfl_xor_sync(0xffffffffu, aks[i], 2);
    }
    if ((lane & 3) == 0) {
        const int r = lane >> 2;
        asw[w][r] = aks[0];
        asw[w][8 + r] = aks[1];
        asw[w][16 + r] = aks[2];
        asw[w][24 + r] = aks[3];
    }
    CBAR();
    if (tid < K) {
        const int wmk = tid >> 5, kk = tid & 31;
        g_asum_part[(n * NCHUNK + chunk) * K + tid] =
            asw[wmk * 4 + 0][kk] + asw[wmk * 4 + 1][kk] +
            asw[wmk * 4 + 2][kk] + asw[wmk * 4 + 3][kk];
    }

    {
        float* gp = g_part + (size_t)(n * NCHUNK + chunk) * KE * C;
#pragma unroll
        for (int mt = 0; mt < 2; ++mt)
#pragma unroll
            for (int f = 0; f < 4; ++f) {
                const int c = wn * 32 + f * 8 + 2 * (lane & 3);
                const int kr = k0 + 16 * mt;
                float* dd = d2[mt * 4 + f];
                *(float2*)(gp + kr * C + c) = make_float2(dd[0], dd[1]);
                if (kr + 8 < KE)
                    *(float2*)(gp + (kr + 8) * C + c) = make_float2(dd[2], dd[3]);
            }
    }
}

__global__ __launch_bounds__(256)
void reduce_part() {
    const int n = blockIdx.x;
    const int idx = blockIdx.y * 256 + threadIdx.x;   // 0..1791 float4 units (KE*C/4)
    const float4* src = (const float4*)g_part + (size_t)n * NCHUNK * 1792 + idx;
    float4 acc = make_float4(0.f, 0.f, 0.f, 0.f);
#pragma unroll
    for (int t = 0; t < NCHUNK; ++t) {
        float4 v = src[(size_t)t * 1792];
        acc.x += v.x; acc.y += v.y; acc.z += v.z; acc.w += v.w;
    }
    ((float4*)g_vlad)[(size_t)n * 1792 + idx] = acc;
}

__global__ __launch_bounds__(512)
void netvlad_finalize(const float* __restrict__ centroids, float* __restrict__ out) {
    __shared__ float ys[KE * C];
    __shared__ float colss[16][C];
    __shared__ float colinv[C];
    __shared__ float asl[KE];
    __shared__ float red[4];
    __shared__ float s_inv2;

    const int n = blockIdx.x, tid = threadIdx.x;

    if (tid < KE) {
        float s = 0.0f;
        const float* ap = g_asum_part + (size_t)n * NCHUNK * K + tid;
#pragma unroll
        for (int t = 0; t < NCHUNK; ++t) s += ap[t * K];
        asl[tid] = s;
    }
    __syncthreads();

    const int cg = (tid & 31) * 4;
    float4 ss4 = make_float4(0.f, 0.f, 0.f, 0.f);
#pragma unroll
    for (int r = 0; r < 4; ++r) {
        int e4 = tid + r * 512;
        if (e4 < 1792) {
            int k = e4 >> 5;
            float a = asl[k];
            float4 s = ((const float4*)g_vlad)[(size_t)n * 1792 + e4];
            float4 ce = *(const float4*)(centroids + k * C + cg);
            float4 y;
            y.x = s.x - a * ce.x; y.y = s.y - a * ce.y;
            y.z = s.z - a * ce.z; y.w = s.w - a * ce.w;
            *(float4*)(ys + e4 * 4) = y;
            ss4.x += y.x * y.x; ss4.y += y.y * y.y;
            ss4.z += y.z * y.z; ss4.w += y.w * y.w;
        }
    }
    *(float4*)&colss[tid >> 5][cg] = ss4;
    __syncthreads();

    float gs = 0.0f;
    if (tid < C) {
        float cs = 0.0f;
#pragma unroll
        for (int g = 0; g < 16; ++g) cs += colss[g][tid];
        float i1 = 1.0f / fmaxf(sqrtf(cs), 1e-12f);
        gs = cs * i1 * i1;
        colinv[tid] = i1;
    }
    __syncthreads();
#pragma unroll
    for (int off = 16; off; off >>= 1) gs += __shfl_down_sync(0xffffffffu, gs, off);
    if (tid < C && (tid & 31) == 0) red[tid >> 5] = gs;
    __syncthreads();
    if (tid == 0) {
        float t = red[0] + red[1] + red[2] + red[3];
        s_inv2 = 1.0f / fmaxf(sqrtf(t), 1e-12f);
    }
    __syncthreads();
    const float inv2 = s_inv2;
    float* op = out + (size_t)n * KE * C;
    for (int idx = tid; idx < KE * C; idx += 512)
        op[idx] = ys[idx] * colinv[idx & 127] * inv2;
}

extern "C" void kernel_launch(void* const* d_in, const int* in_sizes, int n_in,
                              void* d_out, int out_size) {
    const float* x      = (const float*)d_in[0];
    const float* conv_w = (const float*)d_in[1];
    const float* conv_b = (const float*)d_in[2];
    const float* cen    = (const float*)d_in[3];
    float* out = (float*)d_out;

    cudaFuncSetAttribute(netvlad_mma, cudaFuncAttributeMaxDynamicSharedMemorySize, SMEM_DYN);

    netvlad_mma<<<dim3(NB, NCHUNK), NTHR, SMEM_DYN>>>(x, conv_w, conv_b);
    reduce_part<<<dim3(NB, 7), 256>>>();
    netvlad_finalize<<<NB, 512>>>(cen, out);
}